// round 2
// baseline (speedup 1.0000x reference)
#include <cuda_runtime.h>

// Problem constants (fixed-shape instance)
#define BB 16
#define CC 192
#define HH 224
#define WW 224
#define SS 196

#define CCHUNK 32
#define ROWCHUNKS 8
#define ROWS_PER (HH / ROWCHUNKS)   // 28
#define W4 (WW / 4)                 // 56

__device__ float g_counts[BB * SS];

// ---------------- Kernel 1: zero sums (d_out) and counts ----------------
__global__ void zero_kernel(float* __restrict__ out) {
    const int n = BB * SS * CC;
    int idx = blockIdx.x * blockDim.x + threadIdx.x;
    int stride = gridDim.x * blockDim.x;
    for (int i = idx; i < n; i += stride) out[i] = 0.0f;
    for (int i = idx; i < BB * SS; i += stride) g_counts[i] = 0.0f;
}

// ---------------- Kernel 2: segment-sum accumulation ----------------
// grid: (ROWCHUNKS, CC/CCHUNK, BB), block: 256
// Per-CTA privatized smem accumulator acc[c][s]; flush via global atomics.
__global__ __launch_bounds__(256) void accum_kernel(
    const float* __restrict__ feat,       // (B, C, H, W) fp32
    const int* __restrict__ seg,          // (B, H, W) int32 (JAX x64 disabled!)
    float* __restrict__ out)              // (B, S, C) fp32 (sums)
{
    __shared__ float acc[CCHUNK][SS];     // [channel][segment]
    __shared__ float scnt[SS];
    __shared__ int   sseg[WW];

    const int tid = threadIdx.x;
    const int b   = blockIdx.z;
    const int c0  = blockIdx.y * CCHUNK;
    const int h0  = blockIdx.x * ROWS_PER;
    const bool docnt = (blockIdx.y == 0);

    for (int i = tid; i < CCHUNK * SS; i += 256) (&acc[0][0])[i] = 0.0f;
    for (int i = tid; i < SS; i += 256) scnt[i] = 0.0f;
    __syncthreads();

    for (int r = 0; r < ROWS_PER; ++r) {
        const int h = h0 + r;
        if (tid < WW) {
            int s = seg[((size_t)b * HH + h) * WW + tid];
            s = min(max(s, 0), SS - 1);   // defensive clamp
            sseg[tid] = s;
            if (docnt) atomicAdd(&scnt[s], 1.0f);
        }
        __syncthreads();

        // channel-major base for this (b, c0.., h) row; row start is 128B-aligned (W*4 = 896B)
        const float4* __restrict__ base =
            (const float4*)(feat + ((size_t)(b * CC + c0) * HH + h) * WW);

        // 32 channels x 56 float4 = 1792 vector loads per row, 256 threads -> 7 iters
        #pragma unroll 1
        for (int i = tid; i < CCHUNK * W4; i += 256) {
            int c  = i / W4;
            int w4 = i - c * W4;
            float4 v = base[(size_t)c * (HH * (size_t)WW / 4) + w4];
            int wb = w4 * 4;
            atomicAdd(&acc[c][sseg[wb + 0]], v.x);
            atomicAdd(&acc[c][sseg[wb + 1]], v.y);
            atomicAdd(&acc[c][sseg[wb + 2]], v.z);
            atomicAdd(&acc[c][sseg[wb + 3]], v.w);
        }
        __syncthreads();
    }

    // Flush smem accumulator to global sums (d_out acting as sums buffer)
    for (int i = tid; i < CCHUNK * SS; i += 256) {
        int c = i / SS;
        int s = i - c * SS;
        atomicAdd(&out[((size_t)b * SS + s) * CC + c0 + c], acc[c][s]);
    }
    if (docnt) {
        for (int i = tid; i < SS; i += 256)
            atomicAdd(&g_counts[b * SS + i], scnt[i]);
    }
}

// ---------------- Kernel 3: finalize (divide by count, add positional embedding) ----------------
__global__ void finalize_kernel(
    float* __restrict__ out,                   // (B, S, C) sums -> final
    const float* __restrict__ centroid,        // (B, S, 2)
    const float* __restrict__ posW,            // (2, C)
    const float* __restrict__ posb)            // (C,)
{
    int idx = blockIdx.x * blockDim.x + threadIdx.x;
    if (idx >= BB * SS * CC) return;
    int c  = idx % CC;
    int bs = idx / CC;
    float cnt = g_counts[bs];
    float cx = centroid[bs * 2 + 0] * (1.0f / WW);
    float cy = centroid[bs * 2 + 1] * (1.0f / HH);
    float pos = fmaf(cx, posW[c], fmaf(cy, posW[CC + c], posb[c]));
    out[idx] = out[idx] / fmaxf(cnt, 1.0f) + pos;
}

extern "C" void kernel_launch(void* const* d_in, const int* in_sizes, int n_in,
                              void* d_out, int out_size)
{
    // inputs: 0=img(unused) 1=features 2=segments(int32) 3=centroid_coords 4=pos_W 5=pos_b 6=max_segments
    const float* feat     = (const float*)d_in[1];
    const int*   seg      = (const int*)d_in[2];
    const float* centroid = (const float*)d_in[3];
    const float* posW     = (const float*)d_in[4];
    const float* posb     = (const float*)d_in[5];
    float* out = (float*)d_out;

    (void)in_sizes; (void)n_in; (void)out_size;

    zero_kernel<<<1024, 256>>>(out);

    dim3 grid(ROWCHUNKS, CC / CCHUNK, BB);
    accum_kernel<<<grid, 256>>>(feat, seg, out);

    int n = BB * SS * CC;
    finalize_kernel<<<(n + 255) / 256, 256>>>(out, centroid, posW, posb);
}

// round 3
// speedup vs baseline: 1.1241x; 1.1241x over previous
#include <cuda_runtime.h>
#include <cstdint>

// Problem constants (fixed-shape instance)
#define BB 16
#define CC 192
#define HH 224
#define WW 224
#define SS 196

#define ROWCHUNKS 16
#define ROWS_PER (HH / ROWCHUNKS)       // 14
#define PIX (ROWS_PER * WW)             // 3136
#define PIX4 (PIX / 4)                  // 784
#define CCHUNK 32
#define NCHUNKS (CC / CCHUNK)           // 6
#define NC_PASS 4
#define NPASS (CCHUNK / NC_PASS)        // 8
#define NTHREADS 256
#define EPT ((PIX + NTHREADS - 1) / NTHREADS)  // 13

// dyn smem: pix[NC_PASS][PIX] floats | sorted[PIX] int | hist[SS] int | scan[NTHREADS] int
#define SMEM_BYTES ((NC_PASS * PIX + PIX + SS + NTHREADS) * 4)

__device__ float g_counts[BB * SS];

__device__ __forceinline__ void red_add_v4(float* addr, float a, float b, float c, float d) {
    asm volatile("red.global.add.v4.f32 [%0], {%1,%2,%3,%4};"
                 :: "l"(addr), "f"(a), "f"(b), "f"(c), "f"(d) : "memory");
}

// ---------------- Kernel 1: zero sums (d_out) and counts ----------------
__global__ void zero_kernel(float* __restrict__ out) {
    const int n = BB * SS * CC;
    int idx = blockIdx.x * blockDim.x + threadIdx.x;
    int stride = gridDim.x * blockDim.x;
    for (int i = idx; i < n; i += stride) out[i] = 0.0f;
    for (int i = idx; i < BB * SS; i += stride) g_counts[i] = 0.0f;
}

// ---------------- Kernel 2: sort + segmented reduction ----------------
// grid: (ROWCHUNKS, NCHUNKS, BB), block: 256
__global__ __launch_bounds__(NTHREADS) void accum_kernel(
    const float* __restrict__ feat,   // (B, C, H, W) fp32
    const int* __restrict__ seg,      // (B, H, W) int32
    float* __restrict__ out)          // (B, S, C) fp32 (sums)
{
    extern __shared__ char smem_raw[];
    float* pix     = (float*)smem_raw;                       // NC_PASS * PIX floats
    int*   sorted  = (int*)(pix + NC_PASS * PIX);            // PIX
    int*   hist    = sorted + PIX;                           // SS
    int*   scanbuf = hist + SS;                              // NTHREADS

    const int tid = threadIdx.x;
    const int b   = blockIdx.z;
    const int c0  = blockIdx.y * CCHUNK;
    const int h0  = blockIdx.x * ROWS_PER;

    // ---- Phase 1: counting sort of pixels by segment id ----
    int* segtmp = (int*)pix;  // scratch: PIX ints (pix not yet used)

    for (int i = tid; i < SS; i += NTHREADS) hist[i] = 0;
    __syncthreads();

    const int* segbase = seg + ((size_t)b * HH + h0) * WW;   // contiguous PIX ints
    for (int i = tid; i < PIX; i += NTHREADS) {
        int s = segbase[i];
        s = min(max(s, 0), SS - 1);
        segtmp[i] = s;
        atomicAdd(&hist[s], 1);
    }
    __syncthreads();

    // counts contribution (one c-chunk only)
    if (blockIdx.y == 0) {
        for (int i = tid; i < SS; i += NTHREADS)
            atomicAdd(&g_counts[b * SS + i], (float)hist[i]);
    }

    // block-wide exclusive scan of hist (SS <= NTHREADS)
    int v = (tid < SS) ? hist[tid] : 0;
    scanbuf[tid] = v;
    __syncthreads();
    #pragma unroll
    for (int d = 1; d < NTHREADS; d <<= 1) {
        int t = (tid >= d) ? scanbuf[tid - d] : 0;
        __syncthreads();
        scanbuf[tid] += t;
        __syncthreads();
    }
    if (tid < SS) hist[tid] = scanbuf[tid] - v;  // exclusive offsets
    __syncthreads();

    // scatter: sorted[pos] = (s << 16) | local_pixel_idx
    for (int i = tid; i < PIX; i += NTHREADS) {
        int s = segtmp[i];
        int pos = atomicAdd(&hist[s], 1);
        sorted[pos] = (s << 16) | i;
    }

    // ---- Phase 2: channel passes ----
    const float* featbase = feat + ((size_t)(b * CC + c0) * HH + h0) * WW;
    const size_t plane = (size_t)HH * WW;

    const int start = tid * EPT;
    const int end   = min(start + EPT, PIX);

    for (int pass = 0; pass < NPASS; ++pass) {
        const int cbase = pass * NC_PASS;
        __syncthreads();  // previous pass readers done / sort scratch done

        // stage NC_PASS feature planes (coalesced float4)
        #pragma unroll
        for (int k = 0; k < NC_PASS; ++k) {
            const float4* src = (const float4*)(featbase + (size_t)(cbase + k) * plane);
            float4* dst = (float4*)(pix + k * PIX);
            #pragma unroll 1
            for (int i = tid; i < PIX4; i += NTHREADS) dst[i] = src[i];
        }
        __syncthreads();

        if (start < PIX) {
            float a0 = 0.f, a1 = 0.f, a2 = 0.f, a3 = 0.f;
            int cur = -1;
            for (int i = start; i < end; ++i) {
                int e = sorted[i];
                int s = e >> 16;
                int idx = e & 0xFFFF;
                float v0 = pix[idx];
                float v1 = pix[PIX + idx];
                float v2 = pix[2 * PIX + idx];
                float v3 = pix[3 * PIX + idx];
                if (s != cur) {
                    if (cur >= 0) {
                        float* o = &out[((size_t)b * SS + cur) * CC + c0 + cbase];
                        red_add_v4(o, a0, a1, a2, a3);
                    }
                    cur = s; a0 = v0; a1 = v1; a2 = v2; a3 = v3;
                } else {
                    a0 += v0; a1 += v1; a2 += v2; a3 += v3;
                }
            }
            if (cur >= 0) {
                float* o = &out[((size_t)b * SS + cur) * CC + c0 + cbase];
                red_add_v4(o, a0, a1, a2, a3);
            }
        }
    }
}

// ---------------- Kernel 3: finalize (divide by count, add positional embedding) ----------------
__global__ void finalize_kernel(
    float* __restrict__ out,                   // (B, S, C) sums -> final
    const float* __restrict__ centroid,        // (B, S, 2)
    const float* __restrict__ posW,            // (2, C)
    const float* __restrict__ posb)            // (C,)
{
    int idx = blockIdx.x * blockDim.x + threadIdx.x;
    if (idx >= BB * SS * CC) return;
    int c  = idx % CC;
    int bs = idx / CC;
    float cnt = g_counts[bs];
    float cx = centroid[bs * 2 + 0] * (1.0f / WW);
    float cy = centroid[bs * 2 + 1] * (1.0f / HH);
    float pos = fmaf(cx, posW[c], fmaf(cy, posW[CC + c], posb[c]));
    out[idx] = out[idx] / fmaxf(cnt, 1.0f) + pos;
}

extern "C" void kernel_launch(void* const* d_in, const int* in_sizes, int n_in,
                              void* d_out, int out_size)
{
    // inputs: 0=img(unused) 1=features 2=segments(int32) 3=centroid_coords 4=pos_W 5=pos_b 6=max_segments
    const float* feat     = (const float*)d_in[1];
    const int*   seg      = (const int*)d_in[2];
    const float* centroid = (const float*)d_in[3];
    const float* posW     = (const float*)d_in[4];
    const float* posb     = (const float*)d_in[5];
    float* out = (float*)d_out;

    (void)in_sizes; (void)n_in; (void)out_size;

    static bool attr_set = false;
    if (!attr_set) {
        cudaFuncSetAttribute(accum_kernel,
                             cudaFuncAttributeMaxDynamicSharedMemorySize, SMEM_BYTES);
        attr_set = true;
    }

    zero_kernel<<<1024, 256>>>(out);

    dim3 grid(ROWCHUNKS, NCHUNKS, BB);
    accum_kernel<<<grid, NTHREADS, SMEM_BYTES>>>(feat, seg, out);

    int n = BB * SS * CC;
    finalize_kernel<<<(n + 255) / 256, 256>>>(out, centroid, posW, posb);
}

// round 4
// speedup vs baseline: 2.3423x; 2.0837x over previous
#include <cuda_runtime.h>
#include <cstdint>

// Problem constants (fixed-shape instance)
#define BB 16
#define CC 192
#define HH 224
#define WW 224
#define SS 196

#define ROWCHUNKS 16
#define ROWS_PER (HH / ROWCHUNKS)     // 14
#define PIX (ROWS_PER * WW)           // 3136
#define PIX4 (PIX / 4)                // 784
#define PLANE4 (HH * WW / 4)          // 12544

#define NC 8                          // channels staged per group
#define NGROUPS (CC / NC)             // 24
#define STRIDE 3140                   // padded plane stride (floats), %4==0 for STS.128, %32==4
#define NTH 512
#define NWARP (NTH / 32)              // 16
#define NSUB (NWARP * 16)             // 256 substreams (16 per warp)
#define EPT 13                        // ceil(PIX / NSUB)
#define RPT 13                        // ceil(PIX4*NC / NTH) staging float4 per thread

// dyn smem: pix[NC][STRIDE] | sorted[PIX] | hist[SS] | scanbuf[NTH]
#define SMEM_BYTES ((NC * STRIDE + PIX + SS + NTH) * 4)

__device__ float g_counts[BB * SS];

// ---------------- Kernel 1: zero sums (d_out) and counts ----------------
__global__ void zero_kernel(float* __restrict__ out) {
    const int n = BB * SS * CC;
    int idx = blockIdx.x * blockDim.x + threadIdx.x;
    int stride = gridDim.x * blockDim.x;
    for (int i = idx; i < n; i += stride) out[i] = 0.0f;
    for (int i = idx; i < BB * SS; i += stride) g_counts[i] = 0.0f;
}

// ---------------- Kernel 2: sort once + multi-channel segmented reduction ----------------
// grid: (ROWCHUNKS, 1, BB), block: 512
__global__ __launch_bounds__(NTH) void accum_kernel(
    const float* __restrict__ feat,   // (B, C, H, W) fp32
    const int* __restrict__ seg,      // (B, H, W) int32
    float* __restrict__ out)          // (B, S, C) fp32 (sums)
{
    extern __shared__ char smem_raw[];
    float* pix     = (float*)smem_raw;                 // NC * STRIDE floats
    int*   sorted  = (int*)(pix + NC * STRIDE);        // PIX
    int*   hist    = sorted + PIX;                     // SS
    int*   scanbuf = hist + SS;                        // NTH

    const int tid = threadIdx.x;
    const int b   = blockIdx.z;
    const int h0  = blockIdx.x * ROWS_PER;

    // ================= Phase 1: counting sort by segment id (once per chunk) =================
    int* segtmp = (int*)pix;  // scratch (pix unused yet), PIX ints

    for (int i = tid; i < SS; i += NTH) hist[i] = 0;
    __syncthreads();

    const int* segbase = seg + ((size_t)b * HH + h0) * WW;   // contiguous PIX ints
    for (int i = tid; i < PIX; i += NTH) {
        int s = segbase[i];
        s = min(max(s, 0), SS - 1);
        segtmp[i] = s;
        atomicAdd(&hist[s], 1);
    }
    __syncthreads();

    // counts (each CTA owns a unique (b, rowchunk))
    for (int i = tid; i < SS; i += NTH)
        atomicAdd(&g_counts[b * SS + i], (float)hist[i]);

    // block-wide exclusive scan of hist (SS <= NTH)
    int v = (tid < SS) ? hist[tid] : 0;
    scanbuf[tid] = v;
    __syncthreads();
    #pragma unroll
    for (int d = 1; d < NTH; d <<= 1) {
        int t = (tid >= d) ? scanbuf[tid - d] : 0;
        __syncthreads();
        scanbuf[tid] += t;
        __syncthreads();
    }
    if (tid < SS) hist[tid] = scanbuf[tid] - v;  // exclusive offsets
    __syncthreads();

    // scatter: sorted[pos] = (s << 12) | local_pixel_idx  (idx < 4096)
    for (int i = tid; i < PIX; i += NTH) {
        int s = segtmp[i];
        int pos = atomicAdd(&hist[s], 1);
        sorted[pos] = (s << 12) | i;
    }
    // NOTE: segtmp (in pix) is dead after this; sync before first STS below.

    // ================= Phase 2: channel groups with register prefetch =================
    const float4* featbase4 =
        (const float4*)(feat + ((size_t)b * CC * HH + h0) * WW);
    // group g, channel-in-group c -> float4 index (g*NC + c)*PLANE4 + w4

    // substream decomposition
    const int lane = tid & 31;
    const int wid  = tid >> 5;
    const int q    = lane & 1;          // channel quad: channels 4q..4q+3
    const int sub  = (wid << 4) | (lane >> 1);   // 0..255
    const int start = sub * EPT;
    const int end   = min(start + EPT, PIX);

    float4 rbuf[RPT];

    // prologue: prefetch group 0
    #pragma unroll
    for (int j = 0; j < RPT; ++j) {
        int gi = tid + j * NTH;
        if (gi < PIX4 * NC) {
            int c  = gi / PIX4;
            int w4 = gi - c * PIX4;
            rbuf[j] = featbase4[(size_t)c * PLANE4 + w4];
        }
    }

    float* obase0 = out + (size_t)b * SS * CC + 4 * q;  // + g*NC + cur*CC at flush

    for (int g = 0; g < NGROUPS; ++g) {
        __syncthreads();   // previous gather (or sort scratter) done with pix

        // stage regs -> smem (STS.128, 16B aligned since STRIDE%4==0)
        #pragma unroll
        for (int j = 0; j < RPT; ++j) {
            int gi = tid + j * NTH;
            if (gi < PIX4 * NC) {
                int c  = gi / PIX4;
                int w4 = gi - c * PIX4;
                *(float4*)(pix + c * STRIDE + 4 * w4) = rbuf[j];
            }
        }

        // prefetch next group (latency hidden behind gather)
        if (g + 1 < NGROUPS) {
            const float4* nxt = featbase4 + (size_t)(g + 1) * NC * PLANE4;
            #pragma unroll
            for (int j = 0; j < RPT; ++j) {
                int gi = tid + j * NTH;
                if (gi < PIX4 * NC) {
                    int c  = gi / PIX4;
                    int w4 = gi - c * PIX4;
                    rbuf[j] = nxt[(size_t)c * PLANE4 + w4];
                }
            }
        }
        __syncthreads();   // staged data visible

        // gather: each (sub, q) walks sorted[start..end), accumulating quad in regs
        if (start < PIX) {
            const float* p0 = pix + (4 * q + 0) * STRIDE;
            const float* p1 = pix + (4 * q + 1) * STRIDE;
            const float* p2 = pix + (4 * q + 2) * STRIDE;
            const float* p3 = pix + (4 * q + 3) * STRIDE;
            float* obase = obase0 + g * NC;

            int e0 = sorted[start];
            int cur = e0 >> 12;
            float a0 = 0.f, a1 = 0.f, a2 = 0.f, a3 = 0.f;

            for (int i = start; i < end; ++i) {
                int e = sorted[i];
                int s = e >> 12;
                int idx = e & 4095;
                float v0 = p0[idx];
                float v1 = p1[idx];
                float v2 = p2[idx];
                float v3 = p3[idx];
                // predicated flush of previous run when segment changes
                float* oaddr = obase + (size_t)cur * CC;
                asm volatile(
                    "{ .reg .pred p; setp.ne.s32 p, %0, %1;\n\t"
                    "@p red.global.add.v4.f32 [%2], {%3,%4,%5,%6}; }"
                    :: "r"(s), "r"(cur), "l"(oaddr),
                       "f"(a0), "f"(a1), "f"(a2), "f"(a3) : "memory");
                bool nb = (s != cur);
                a0 = nb ? v0 : a0 + v0;
                a1 = nb ? v1 : a1 + v1;
                a2 = nb ? v2 : a2 + v2;
                a3 = nb ? v3 : a3 + v3;
                cur = s;
            }
            // epilogue flush
            float* oaddr = obase + (size_t)cur * CC;
            asm volatile(
                "red.global.add.v4.f32 [%0], {%1,%2,%3,%4};"
                :: "l"(oaddr), "f"(a0), "f"(a1), "f"(a2), "f"(a3) : "memory");
        }
    }
}

// ---------------- Kernel 3: finalize (divide by count, add positional embedding) ----------------
__global__ void finalize_kernel(
    float* __restrict__ out,                   // (B, S, C) sums -> final
    const float* __restrict__ centroid,        // (B, S, 2)
    const float* __restrict__ posW,            // (2, C)
    const float* __restrict__ posb)            // (C,)
{
    int idx = blockIdx.x * blockDim.x + threadIdx.x;
    if (idx >= BB * SS * CC) return;
    int c  = idx % CC;
    int bs = idx / CC;
    float cnt = g_counts[bs];
    float cx = centroid[bs * 2 + 0] * (1.0f / WW);
    float cy = centroid[bs * 2 + 1] * (1.0f / HH);
    float pos = fmaf(cx, posW[c], fmaf(cy, posW[CC + c], posb[c]));
    out[idx] = out[idx] / fmaxf(cnt, 1.0f) + pos;
}

extern "C" void kernel_launch(void* const* d_in, const int* in_sizes, int n_in,
                              void* d_out, int out_size)
{
    // inputs: 0=img(unused) 1=features 2=segments(int32) 3=centroid_coords 4=pos_W 5=pos_b 6=max_segments
    const float* feat     = (const float*)d_in[1];
    const int*   seg      = (const int*)d_in[2];
    const float* centroid = (const float*)d_in[3];
    const float* posW     = (const float*)d_in[4];
    const float* posb     = (const float*)d_in[5];
    float* out = (float*)d_out;

    (void)in_sizes; (void)n_in; (void)out_size;

    static bool attr_set = false;
    if (!attr_set) {
        cudaFuncSetAttribute(accum_kernel,
                             cudaFuncAttributeMaxDynamicSharedMemorySize, SMEM_BYTES);
        attr_set = true;
    }

    zero_kernel<<<1024, 256>>>(out);

    dim3 grid(ROWCHUNKS, 1, BB);
    accum_kernel<<<grid, NTH, SMEM_BYTES>>>(feat, seg, out);

    int n = BB * SS * CC;
    finalize_kernel<<<(n + 255) / 256, 256>>>(out, centroid, posW, posb);
}

// round 5
// speedup vs baseline: 2.5624x; 1.0939x over previous
#include <cuda_runtime.h>
#include <cstdint>

// Problem constants (fixed-shape instance)
#define BB 16
#define CC 192
#define HH 224
#define WW 224
#define SS 196

#define ROWCHUNKS 16
#define ROWS_PER (HH / ROWCHUNKS)     // 14
#define PIX (ROWS_PER * WW)           // 3136
#define PLANE_BYTES (PIX * 4)         // 12544 (contiguous per channel per chunk)

#define NC 4                          // channels per group
#define NGROUPS (CC / NC)             // 48
#define NSTAGE 3                      // pipeline depth
#define STRIDE 3144                   // padded plane stride (floats); %32==8, *4 %16==0
#define GROUP_BYTES (NC * PLANE_BYTES) // 50176
#define NTH 512

// dyn smem (floats): ring[NSTAGE*NC*STRIDE] | sorted[PIX] | hist[SS] | scanbuf[NTH] | mbars
#define RING_FLOATS (NSTAGE * NC * STRIDE)
#define SMEM_FLOATS (RING_FLOATS + PIX + SS + NTH)
#define SMEM_BYTES (SMEM_FLOATS * 4 + 64)

__device__ float g_counts[BB * SS];

__device__ __forceinline__ uint32_t smem_u32(const void* p) {
    uint32_t a;
    asm("{ .reg .u64 t; cvta.to.shared.u64 t, %1; cvt.u32.u64 %0, t; }" : "=r"(a) : "l"(p));
    return a;
}
__device__ __forceinline__ void mbar_init(uint32_t mbar, uint32_t cnt) {
    asm volatile("mbarrier.init.shared.b64 [%0], %1;" :: "r"(mbar), "r"(cnt) : "memory");
}
__device__ __forceinline__ void mbar_expect_tx(uint32_t mbar, uint32_t bytes) {
    asm volatile("mbarrier.arrive.expect_tx.shared.b64 _, [%0], %1;" :: "r"(mbar), "r"(bytes) : "memory");
}
__device__ __forceinline__ void mbar_wait(uint32_t mbar, uint32_t parity) {
    asm volatile(
        "{\n\t"
        ".reg .pred P;\n\t"
        "W_%=:\n\t"
        "mbarrier.try_wait.parity.acquire.cta.shared::cta.b64 P, [%0], %1, 0x989680;\n\t"
        "@P bra D_%=;\n\t"
        "bra W_%=;\n\t"
        "D_%=:\n\t"
        "}" :: "r"(mbar), "r"(parity) : "memory");
}
__device__ __forceinline__ void bulk_g2s(uint32_t dst, const void* src, uint32_t bytes, uint32_t mbar) {
    asm volatile("cp.async.bulk.shared::cta.global.mbarrier::complete_tx::bytes [%0], [%1], %2, [%3];"
                 :: "r"(dst), "l"(src), "r"(bytes), "r"(mbar) : "memory");
}

// ---------------- Kernel 1: zero sums (d_out) and counts ----------------
__global__ void zero_kernel(float* __restrict__ out) {
    const int n = BB * SS * CC;
    int idx = blockIdx.x * blockDim.x + threadIdx.x;
    int stride = gridDim.x * blockDim.x;
    for (int i = idx; i < n; i += stride) out[i] = 0.0f;
    for (int i = idx; i < BB * SS; i += stride) g_counts[i] = 0.0f;
}

// ---------------- Kernel 2: sort once + TMA-pipelined segmented reduction ----------------
// grid: (ROWCHUNKS, 1, BB), block: 512
__global__ __launch_bounds__(NTH) void accum_kernel(
    const float* __restrict__ feat,   // (B, C, H, W) fp32
    const int* __restrict__ seg,      // (B, H, W) int32
    float* __restrict__ out)          // (B, S, C) fp32 (sums)
{
    extern __shared__ char smem_raw[];
    float* ring    = (float*)smem_raw;               // NSTAGE * NC * STRIDE
    int*   sorted  = (int*)(ring + RING_FLOATS);     // PIX
    int*   hist    = sorted + PIX;                   // SS
    int*   scanbuf = hist + SS;                      // NTH
    unsigned long long* mbars = (unsigned long long*)(scanbuf + NTH);  // NSTAGE

    const int tid = threadIdx.x;
    const int b   = blockIdx.z;
    const int h0  = blockIdx.x * ROWS_PER;

    const uint32_t mbar0 = smem_u32(mbars);

    if (tid == 0) {
        #pragma unroll
        for (int s = 0; s < NSTAGE; ++s) mbar_init(mbar0 + 8 * s, 1);
    }

    // ================= Phase 1: counting sort by segment id (once per chunk) =================
    int* segtmp = (int*)ring;  // scratch (ring unused yet), PIX ints

    for (int i = tid; i < SS; i += NTH) hist[i] = 0;
    __syncthreads();

    const int* segbase = seg + ((size_t)b * HH + h0) * WW;   // contiguous PIX ints
    for (int i = tid; i < PIX; i += NTH) {
        int s = segbase[i];
        s = min(max(s, 0), SS - 1);
        segtmp[i] = s;
        atomicAdd(&hist[s], 1);
    }
    __syncthreads();

    // counts (each CTA owns a unique (b, rowchunk))
    for (int i = tid; i < SS; i += NTH)
        atomicAdd(&g_counts[b * SS + i], (float)hist[i]);

    // block-wide exclusive scan of hist (SS <= NTH)
    int v = (tid < SS) ? hist[tid] : 0;
    scanbuf[tid] = v;
    __syncthreads();
    #pragma unroll
    for (int d = 1; d < NTH; d <<= 1) {
        int t = (tid >= d) ? scanbuf[tid - d] : 0;
        __syncthreads();
        scanbuf[tid] += t;
        __syncthreads();
    }
    if (tid < SS) hist[tid] = scanbuf[tid] - v;  // exclusive offsets
    __syncthreads();

    // scatter: sorted[pos] = (s << 12) | local_pixel_idx  (idx < 4096)
    for (int i = tid; i < PIX; i += NTH) {
        int s = segtmp[i];
        int pos = atomicAdd(&hist[s], 1);
        sorted[pos] = (s << 12) | i;
    }
    __syncthreads();   // sort done; ring scratch dead -> safe for TMA

    // ================= Phase 2: pipelined channel groups =================
    const float* featbase = feat + ((size_t)b * CC * HH + h0) * WW;  // + c*HH*WW
    const size_t plane = (size_t)HH * WW;
    const uint32_t ring_s = smem_u32(ring);

    // prologue: issue TMAs for groups 0..NSTAGE-1
    if (tid == 0) {
        #pragma unroll
        for (int s = 0; s < NSTAGE; ++s) {
            mbar_expect_tx(mbar0 + 8 * s, GROUP_BYTES);
            #pragma unroll
            for (int c = 0; c < NC; ++c) {
                bulk_g2s(ring_s + (uint32_t)((s * NC + c) * STRIDE) * 4,
                         featbase + (size_t)(s * NC + c) * plane,
                         PLANE_BYTES, mbar0 + 8 * s);
            }
        }
    }

    // private sorted window: exact partition, PIX/NTH = 6.125 = 49/8
    const int start = (tid * 49) >> 3;
    const int end   = ((tid + 1) * 49) >> 3;

    float* obase0 = out + (size_t)b * SS * CC;

    for (int g = 0; g < NGROUPS; ++g) {
        const int st = g % NSTAGE;
        const uint32_t mb = mbar0 + 8 * st;
        mbar_wait(mb, (g / NSTAGE) & 1);

        const float* p0 = ring + (st * NC + 0) * STRIDE;
        const float* p1 = ring + (st * NC + 1) * STRIDE;
        const float* p2 = ring + (st * NC + 2) * STRIDE;
        const float* p3 = ring + (st * NC + 3) * STRIDE;
        float* obase = obase0 + g * NC;

        int e0 = sorted[start];
        int cur = e0 >> 12;
        float a0 = 0.f, a1 = 0.f, a2 = 0.f, a3 = 0.f;

        for (int i = start; i < end; ++i) {
            int e = sorted[i];
            int s = e >> 12;
            int idx = e & 4095;
            float v0 = p0[idx];
            float v1 = p1[idx];
            float v2 = p2[idx];
            float v3 = p3[idx];
            float* oaddr = obase + (size_t)cur * CC;
            asm volatile(
                "{ .reg .pred p; setp.ne.s32 p, %0, %1;\n\t"
                "@p red.global.add.v4.f32 [%2], {%3,%4,%5,%6}; }"
                :: "r"(s), "r"(cur), "l"(oaddr),
                   "f"(a0), "f"(a1), "f"(a2), "f"(a3) : "memory");
            bool nb = (s != cur);
            a0 = nb ? v0 : a0 + v0;
            a1 = nb ? v1 : a1 + v1;
            a2 = nb ? v2 : a2 + v2;
            a3 = nb ? v3 : a3 + v3;
            cur = s;
        }
        {
            float* oaddr = obase + (size_t)cur * CC;
            asm volatile(
                "red.global.add.v4.f32 [%0], {%1,%2,%3,%4};"
                :: "l"(oaddr), "f"(a0), "f"(a1), "f"(a2), "f"(a3) : "memory");
        }

        __syncthreads();   // all gathers on buffer st complete before refill

        if (tid == 0 && g + NSTAGE < NGROUPS) {
            const int gn = g + NSTAGE;
            mbar_expect_tx(mb, GROUP_BYTES);
            #pragma unroll
            for (int c = 0; c < NC; ++c) {
                bulk_g2s(ring_s + (uint32_t)((st * NC + c) * STRIDE) * 4,
                         featbase + (size_t)(gn * NC + c) * plane,
                         PLANE_BYTES, mb);
            }
        }
    }
}

// ---------------- Kernel 3: finalize (divide by count, add positional embedding) ----------------
__global__ void finalize_kernel(
    float* __restrict__ out,                   // (B, S, C) sums -> final
    const float* __restrict__ centroid,        // (B, S, 2)
    const float* __restrict__ posW,            // (2, C)
    const float* __restrict__ posb)            // (C,)
{
    int idx = blockIdx.x * blockDim.x + threadIdx.x;
    if (idx >= BB * SS * CC) return;
    int c  = idx % CC;
    int bs = idx / CC;
    float cnt = g_counts[bs];
    float cx = centroid[bs * 2 + 0] * (1.0f / WW);
    float cy = centroid[bs * 2 + 1] * (1.0f / HH);
    float pos = fmaf(cx, posW[c], fmaf(cy, posW[CC + c], posb[c]));
    out[idx] = out[idx] / fmaxf(cnt, 1.0f) + pos;
}

extern "C" void kernel_launch(void* const* d_in, const int* in_sizes, int n_in,
                              void* d_out, int out_size)
{
    // inputs: 0=img(unused) 1=features 2=segments(int32) 3=centroid_coords 4=pos_W 5=pos_b 6=max_segments
    const float* feat     = (const float*)d_in[1];
    const int*   seg      = (const int*)d_in[2];
    const float* centroid = (const float*)d_in[3];
    const float* posW     = (const float*)d_in[4];
    const float* posb     = (const float*)d_in[5];
    float* out = (float*)d_out;

    (void)in_sizes; (void)n_in; (void)out_size;

    static bool attr_set = false;
    if (!attr_set) {
        cudaFuncSetAttribute(accum_kernel,
                             cudaFuncAttributeMaxDynamicSharedMemorySize, SMEM_BYTES);
        attr_set = true;
    }

    zero_kernel<<<1024, 256>>>(out);

    dim3 grid(ROWCHUNKS, 1, BB);
    accum_kernel<<<grid, NTH, SMEM_BYTES>>>(feat, seg, out);

    int n = BB * SS * CC;
    finalize_kernel<<<(n + 255) / 256, 256>>>(out, centroid, posW, posb);
}